// round 10
// baseline (speedup 1.0000x reference)
#include <cuda_runtime.h>
#include <cstdint>
#include <math.h>

#define D_MODEL   256
#define N_HEADS   8
#define LEN_IN    5440
#define LEN_Q     5440
#define BATCH     4
#define M_TOTAL   (BATCH * LEN_Q)   // 21760 = 170 * 128

// k-permutation within groups of 8: pos(k) = [0,4,1,5,2,6,3,7]^-1 mapping
__host__ __device__ __forceinline__ int kperm(int k) {
    return (k & ~7) | ((k & 3) << 1) | ((k >> 2) & 1);
}

// ---------------- scratch (static device globals; no allocation) -------------
__device__ float g_value[(size_t)M_TOTAL * 256];
__device__ float g_off  [(size_t)M_TOTAL * 256];
__device__ float g_attn [(size_t)M_TOTAL * 128];
__device__ float g_mid  [(size_t)M_TOTAL * 256];   // k-permuted + tf32 pre-rounded
// transposed weights [N, K=256] K-major, k-permuted + tf32 pre-rounded
__device__ float g_wvT [256 * 256];
__device__ float g_woT [256 * 256];
__device__ float g_waT [128 * 256];
__device__ float g_wouT[256 * 256];

// ---------------- PTX helpers ------------------------------------------------
__device__ __forceinline__ uint32_t smem_u32(const void* p) {
    uint32_t a;
    asm("{ .reg .u64 t; cvta.to.shared.u64 t, %1; cvt.u32.u64 %0, t; }" : "=r"(a) : "l"(p));
    return a;
}
__device__ __forceinline__ void cp_async16(uint32_t dst, const void* src) {
    asm volatile("cp.async.cg.shared.global [%0], [%1], 16;" :: "r"(dst), "l"(src));
}
#define CP_COMMIT() asm volatile("cp.async.commit_group;" ::: "memory")
#define CP_WAIT(n)  asm volatile("cp.async.wait_group %0;" :: "n"(n) : "memory")

__device__ __forceinline__ uint32_t f2tf(float x) {
    uint32_t r; asm("cvt.rna.tf32.f32 %0, %1;" : "=r"(r) : "f"(x)); return r;
}
__device__ __forceinline__ void mma_tf32(float* c, const uint32_t* a, const uint32_t* b) {
    asm volatile("mma.sync.aligned.m16n8k8.row.col.f32.tf32.tf32.f32 "
        "{%0,%1,%2,%3}, {%4,%5,%6,%7}, {%8,%9}, {%0,%1,%2,%3};"
        : "+f"(c[0]), "+f"(c[1]), "+f"(c[2]), "+f"(c[3])
        : "r"(a[0]), "r"(a[1]), "r"(a[2]), "r"(a[3]), "r"(b[0]), "r"(b[1]));
}

// ------ fused weight transpose + tf32 pre-round + k-permute ------------------
__global__ void transpose_all(const float* __restrict__ Wv, const float* __restrict__ Wo,
                              const float* __restrict__ Wa, const float* __restrict__ Wou,
                              float* __restrict__ WvT, float* __restrict__ WoT,
                              float* __restrict__ WaT, float* __restrict__ WouT) {
    __shared__ float t[32][33];
    const int m = blockIdx.y;
    const float* W; float* Wt; int N;
    if      (m == 0) { W = Wv;  Wt = WvT;  N = 256; }
    else if (m == 1) { W = Wo;  Wt = WoT;  N = 256; }
    else if (m == 2) { W = Wa;  Wt = WaT;  N = 128; }
    else             { W = Wou; Wt = WouT; N = 256; }
    const int bx = (blockIdx.x & 7) * 32;   // n
    const int by = (blockIdx.x >> 3) * 32;  // k
    if (bx >= N) return;
    const int x = threadIdx.x, y = threadIdx.y;
#pragma unroll
    for (int i = 0; i < 32; i += 8) t[y + i][x] = W[(by + y + i) * N + bx + x];
    __syncthreads();
#pragma unroll
    for (int i = 0; i < 32; i += 8)
        Wt[(bx + y + i) * 256 + kperm(by + x)] = __uint_as_float(f2tf(t[x][y + i]));
}

// ---------------- TF32 tensor-core GEMM (high-occupancy small tiles) ---------
// CTA tile 128x64, BK=32, 8 warps (4m x 2n), warp tile 32x32 (8x m16n8k8).
// Double-buffered cp.async, 4 CTA/SM.
#define TSTRIDE  36
#define TILE_A_F (128 * TSTRIDE)
#define TILE_B_F (64 * TSTRIDE)
#define BUF_F    (TILE_A_F + TILE_B_F)
#define SMEM_B   (2 * BUF_F * 4)    // 55,296 B per CTA

template <bool PRE_A>
__global__ void __launch_bounds__(256, 4)
gemm_tc(const float* __restrict__ A0, const float* __restrict__ A1,
        const float* __restrict__ W0, const float* __restrict__ W1, const float* __restrict__ W2,
        const float* __restrict__ b0, const float* __restrict__ b1, const float* __restrict__ b2,
        float* __restrict__ C0, float* __restrict__ C1, float* __restrict__ C2) {
    extern __shared__ float sm[];
    const int tid  = threadIdx.x;
    const int wid  = tid >> 5;
    const int lane = tid & 31;
    const int gid  = lane >> 2;
    const int tg   = lane & 3;
    const int bm   = blockIdx.x * 128;
    const int wm   = (wid & 3) * 32;      // warp m offset
    const int wn   = (wid >> 2) * 32;     // warp n offset

    const float *A, *Wt, *bias; float* C; int NTOT = 256; int bn;
    {
        const int y = blockIdx.y;
        if (!PRE_A) {
            if (y < 4)      { A = A0; Wt = W0; bias = b0; C = C0; bn = y * 64; }
            else if (y < 8) { A = A1; Wt = W1; bias = b1; C = C1; bn = (y - 4) * 64; }
            else            { A = A1; Wt = W2; bias = b2; C = C2; bn = (y - 8) * 64; NTOT = 128; }
        } else              { A = A0; Wt = W0; bias = b0; C = C0; bn = y * 64; }
    }

    const float* Ab = A  + (size_t)bm * 256;
    const float* Bb = Wt + (size_t)bn * 256;
    const uint32_t smb = smem_u32(sm);

    const int lrow = tid >> 3;            // 0..31 (A: +i*32), B uses 0..63 pattern
    const int lcol = (tid & 7) * 4;

    auto load_tile = [&](int buf, int kc) {
        const uint32_t dA = smb + (uint32_t)(buf * BUF_F) * 4;
        const uint32_t dB = dA + (uint32_t)TILE_A_F * 4;
#pragma unroll
        for (int i = 0; i < 4; ++i) {     // A: 128 rows x 8 float4
            const int r = lrow + i * 32;
            cp_async16(dA + (uint32_t)(r * TSTRIDE + lcol) * 4,
                       Ab + (size_t)r * 256 + kc + lcol);
        }
#pragma unroll
        for (int i = 0; i < 2; ++i) {     // B: 64 rows x 8 float4
            const int r = lrow + i * 32;  // 0..63
            cp_async16(dB + (uint32_t)(r * TSTRIDE + lcol) * 4,
                       Bb + (size_t)r * 256 + kc + lcol);
        }
        CP_COMMIT();
    };

    float acc[2][4][4];
#pragma unroll
    for (int mt = 0; mt < 2; ++mt)
#pragma unroll
        for (int nt = 0; nt < 4; ++nt)
#pragma unroll
            for (int i = 0; i < 4; ++i) acc[mt][nt][i] = 0.0f;

    load_tile(0, 0);
#pragma unroll 1
    for (int c = 0; c < 8; ++c) {
        if (c < 7) { load_tile((c + 1) & 1, (c + 1) * 32); CP_WAIT(1); }
        else       { CP_WAIT(0); }
        __syncthreads();

        const float* As = sm + (c & 1) * BUF_F;
        const float* Bs = As + TILE_A_F;
#pragma unroll
        for (int k8 = 0; k8 < 4; ++k8) {
            const int kk = k8 * 8;
            uint32_t bf[4][2];
#pragma unroll
            for (int nt = 0; nt < 4; ++nt) {
                const int nr = wn + nt * 8 + gid;
                const float2 b2 = *(const float2*)&Bs[nr * TSTRIDE + kk + 2 * tg];
                bf[nt][0] = __float_as_uint(b2.x);
                bf[nt][1] = __float_as_uint(b2.y);
            }
            uint32_t af[2][4];
#pragma unroll
            for (int mt = 0; mt < 2; ++mt) {
                const int r0 = wm + mt * 16 + gid;
                if (PRE_A) {
                    const float2 alo = *(const float2*)&As[r0 * TSTRIDE + kk + 2 * tg];
                    const float2 ahi = *(const float2*)&As[(r0 + 8) * TSTRIDE + kk + 2 * tg];
                    af[mt][0] = __float_as_uint(alo.x);
                    af[mt][1] = __float_as_uint(ahi.x);
                    af[mt][2] = __float_as_uint(alo.y);
                    af[mt][3] = __float_as_uint(ahi.y);
                } else {
                    af[mt][0] = f2tf(As[r0 * TSTRIDE + kk + tg]);
                    af[mt][1] = f2tf(As[(r0 + 8) * TSTRIDE + kk + tg]);
                    af[mt][2] = f2tf(As[r0 * TSTRIDE + kk + tg + 4]);
                    af[mt][3] = f2tf(As[(r0 + 8) * TSTRIDE + kk + tg + 4]);
                }
            }
#pragma unroll
            for (int mt = 0; mt < 2; ++mt)
#pragma unroll
                for (int nt = 0; nt < 4; ++nt)
                    mma_tf32(acc[mt][nt], af[mt], bf[nt]);
        }
        __syncthreads();
    }

#pragma unroll
    for (int mt = 0; mt < 2; ++mt) {
        const int row0 = bm + wm + mt * 16 + gid;
#pragma unroll
        for (int nt = 0; nt < 4; ++nt) {
            const int col = bn + wn + nt * 8 + tg * 2;
            const float2 bv = *(const float2*)(bias + col);
            float2 v0, v1;
            v0.x = acc[mt][nt][0] + bv.x;  v0.y = acc[mt][nt][1] + bv.y;
            v1.x = acc[mt][nt][2] + bv.x;  v1.y = acc[mt][nt][3] + bv.y;
            *(float2*)(C + (size_t)row0 * NTOT + col)       = v0;
            *(float2*)(C + (size_t)(row0 + 8) * NTOT + col) = v1;
        }
    }
}

// ---------------- sampling ---------------------------------------------------
__global__ void __launch_bounds__(256)
msda_sample(const float* __restrict__ refp) {
    const int bq   = blockIdx.x;
    const int b    = bq / LEN_Q;
    const int tid  = threadIdx.x;
    const int h    = tid >> 5;
    const int lane = tid & 31;

    __shared__ uint4 s_pk[8][16][2];

    const size_t rowo = (size_t)bq * 256;

    {
        const int ln = lane & 15;           // point id
        const int l  = ln >> 2;             // level

        float logit = g_attn[(size_t)bq * 128 + h * 16 + ln];
        float m = logit;
#pragma unroll
        for (int s = 8; s; s >>= 1) m = fmaxf(m, __shfl_xor_sync(0xffffffffu, m, s, 16));
        float e = __expf(logit - m);
        float ssum = e;
#pragma unroll
        for (int s = 8; s; s >>= 1) ssum += __shfl_xor_sync(0xffffffffu, ssum, s, 16);
        const float aw = e / ssum;

        const int S  = 64 >> l;
        const int st = (l == 0) ? 0 : (l == 1) ? 4096 : (l == 2) ? 5120 : 5376;
        const float fs = (float)S;

        const float rx = refp[(size_t)bq * 8 + l * 2 + 0];
        const float ry = refp[(size_t)bq * 8 + l * 2 + 1];
        const float ox = g_off[rowo + h * 32 + ln * 2 + 0];
        const float oy = g_off[rowo + h * 32 + ln * 2 + 1];

        const float x = fmaf(rx, fs, ox) - 0.5f;
        const float y = fmaf(ry, fs, oy) - 0.5f;
        const float x0f = floorf(x), y0f = floorf(y);
        const int ix0 = (int)x0f, iy0 = (int)y0f;
        const float wx = x - x0f, wy = y - y0f;

        const float fx0 = (unsigned)ix0       < (unsigned)S ? 1.0f : 0.0f;
        const float fx1 = (unsigned)(ix0 + 1) < (unsigned)S ? 1.0f : 0.0f;
        const float fy0 = (unsigned)iy0       < (unsigned)S ? 1.0f : 0.0f;
        const float fy1 = (unsigned)(iy0 + 1) < (unsigned)S ? 1.0f : 0.0f;

        const int cx0 = min(max(ix0, 0), S - 1);
        const int cx1 = min(max(ix0 + 1, 0), S - 1);
        const int cy0 = min(max(iy0, 0), S - 1);
        const int cy1 = min(max(iy0 + 1, 0), S - 1);

        if (lane < 16) {
            uint4 left, right;
            left.x  = (uint32_t)((st + cy0 * S + cx0) * 256);
            left.y  = (uint32_t)((st + cy1 * S + cx0) * 256);
            left.z  = __float_as_uint(aw * (1.0f - wx) * (1.0f - wy) * fx0 * fy0);
            left.w  = __float_as_uint(aw * (1.0f - wx) * wy          * fx0 * fy1);
            right.x = (uint32_t)((st + cy0 * S + cx1) * 256);
            right.y = (uint32_t)((st + cy1 * S + cx1) * 256);
            right.z = __float_as_uint(aw * wx * (1.0f - wy) * fx1 * fy0);
            right.w = __float_as_uint(aw * wx * wy          * fx1 * fy1);
            s_pk[h][ln][0] = left;
            s_pk[h][ln][1] = right;
        }
    }
    __syncwarp();

    const int side = lane >> 4;
    const int cb   = (lane & 15) * 2;       // channel pair within head
    const float* vb = g_value + (size_t)b * (LEN_IN * 256) + h * 32 + cb;

    float a0 = 0.f, a1 = 0.f, a2 = 0.f, a3 = 0.f;
#pragma unroll
    for (int p = 0; p < 16; ++p) {
        const uint4 pk = s_pk[h][p][side];
        const float2 vt = *(const float2*)(vb + pk.x);
        const float2 vo = *(const float2*)(vb + pk.y);
        const float wt = __uint_as_float(pk.z);
        const float wb = __uint_as_float(pk.w);
        a0 = fmaf(wt, vt.x, a0);
        a1 = fmaf(wt, vt.y, a1);
        a2 = fmaf(wb, vo.x, a2);
        a3 = fmaf(wb, vo.y, a3);
    }
    float ox_ = a0 + a2;
    float oy_ = a1 + a3;
    ox_ += __shfl_xor_sync(0xffffffffu, ox_, 16);
    oy_ += __shfl_xor_sync(0xffffffffu, oy_, 16);

    if (lane < 16) {   // store pre-rounded tf32 at k-permuted channel positions
        const int c0 = h * 32 + cb;
        g_mid[rowo + kperm(c0)]     = __uint_as_float(f2tf(ox_));
        g_mid[rowo + kperm(c0 + 1)] = __uint_as_float(f2tf(oy_));
    }
}

// ---------------- launch -----------------------------------------------------
extern "C" void kernel_launch(void* const* d_in, const int* in_sizes, int n_in,
                              void* d_out, int out_size) {
    const float* query   = (const float*)d_in[0];
    const float* refp    = (const float*)d_in[1];
    const float* in_flat = (const float*)d_in[2];
    const float* W_val  = (const float*)d_in[5];
    const float* b_val  = (const float*)d_in[6];
    const float* W_off  = (const float*)d_in[7];
    const float* b_off  = (const float*)d_in[8];
    const float* W_attn = (const float*)d_in[9];
    const float* b_attn = (const float*)d_in[10];
    const float* W_out  = (const float*)d_in[11];
    const float* b_out  = (const float*)d_in[12];
    float* out = (float*)d_out;

    float *pv, *po, *pa, *pm, *wvT, *woT, *waT, *wouT;
    cudaGetSymbolAddress((void**)&pv,  g_value);
    cudaGetSymbolAddress((void**)&po,  g_off);
    cudaGetSymbolAddress((void**)&pa,  g_attn);
    cudaGetSymbolAddress((void**)&pm,  g_mid);
    cudaGetSymbolAddress((void**)&wvT, g_wvT);
    cudaGetSymbolAddress((void**)&woT, g_woT);
    cudaGetSymbolAddress((void**)&waT, g_waT);
    cudaGetSymbolAddress((void**)&wouT, g_wouT);

    cudaFuncSetAttribute(gemm_tc<false>, cudaFuncAttributeMaxDynamicSharedMemorySize, SMEM_B);
    cudaFuncSetAttribute(gemm_tc<true>,  cudaFuncAttributeMaxDynamicSharedMemorySize, SMEM_B);

    transpose_all<<<dim3(64, 4), dim3(32, 8)>>>(W_val, W_off, W_attn, W_out,
                                                wvT, woT, waT, wouT);

    // fused front GEMMs: value (y=0..3), offsets (y=4..7), attn (y=8..9)
    gemm_tc<false><<<dim3(M_TOTAL / 128, 10), 256, SMEM_B>>>(
        in_flat, query, wvT, woT, waT, b_val, b_off, b_attn, pv, po, pa);

    msda_sample<<<M_TOTAL, 256>>>(refp);

    // output projection (A = g_mid, pre-rounded + k-permuted)
    gemm_tc<true><<<dim3(M_TOTAL / 128, 4), 256, SMEM_B>>>(
        pm, nullptr, wouT, nullptr, nullptr, b_out, nullptr, nullptr,
        out, nullptr, nullptr);
}

// round 12
// speedup vs baseline: 1.2963x; 1.2963x over previous
#include <cuda_runtime.h>
#include <cuda_fp16.h>
#include <cstdint>
#include <math.h>

#define D_MODEL   256
#define N_HEADS   8
#define LEN_IN    5440
#define LEN_Q     5440
#define BATCH     4
#define M_TOTAL   (BATCH * LEN_Q)   // 21760 = 1360 * 16

// ---------------- scratch (static device globals; no allocation) -------------
__device__ float g_value[(size_t)M_TOTAL * 256];
__device__ float g_off  [(size_t)M_TOTAL * 256];
__device__ float g_attn [(size_t)M_TOTAL * 128];
// fp16 fragment-native A operands: [M/16][16 k16][32 lanes][8 halfs]
__device__ __align__(16) __half g_qh [(size_t)M_TOTAL * 256];
__device__ __align__(16) __half g_ih [(size_t)M_TOTAL * 256];
__device__ __align__(16) __half g_midh[(size_t)M_TOTAL * 256];
// fp16 fragment-native weights: [N/8][16 k16][32 lanes][4 halfs]
__device__ __align__(16) __half g_wvH [256 * 256];
__device__ __align__(16) __half g_woH [256 * 256];
__device__ __align__(16) __half g_waH [128 * 256];
__device__ __align__(16) __half g_wouH[256 * 256];

// ---------------- PTX helpers ------------------------------------------------
__device__ __forceinline__ uint32_t h2u(__half2 h) {
    return *reinterpret_cast<uint32_t*>(&h);
}
__device__ __forceinline__ uint32_t smem_u32(const void* p) {
    uint32_t a;
    asm("{ .reg .u64 t; cvta.to.shared.u64 t, %1; cvt.u32.u64 %0, t; }" : "=r"(a) : "l"(p));
    return a;
}
__device__ __forceinline__ void cp_async16(uint32_t dst, const void* src) {
    asm volatile("cp.async.cg.shared.global [%0], [%1], 16;" :: "r"(dst), "l"(src));
}
#define CP_COMMIT() asm volatile("cp.async.commit_group;" ::: "memory")
#define CP_WAIT(n)  asm volatile("cp.async.wait_group %0;" :: "n"(n) : "memory")

__device__ __forceinline__ void mma_f16(float* c, const uint32_t* a, const uint32_t* b) {
    asm volatile("mma.sync.aligned.m16n8k16.row.col.f32.f16.f16.f32 "
        "{%0,%1,%2,%3}, {%4,%5,%6,%7}, {%8,%9}, {%0,%1,%2,%3};"
        : "+f"(c[0]), "+f"(c[1]), "+f"(c[2]), "+f"(c[3])
        : "r"(a[0]), "r"(a[1]), "r"(a[2]), "r"(a[3]), "r"(b[0]), "r"(b[1]));
}

// ------ weights: transpose + fp16 + fragment-native [N/8][k16][lane][4h] -----
__global__ void conv_w(const float* __restrict__ Wv, const float* __restrict__ Wo,
                       const float* __restrict__ Wa, const float* __restrict__ Wou,
                       __half* __restrict__ WvH, __half* __restrict__ WoH,
                       __half* __restrict__ WaH, __half* __restrict__ WouH) {
    const int m = blockIdx.y;
    const float* W; __half* Wh; int N;
    if      (m == 0) { W = Wv;  Wh = WvH;  N = 256; }
    else if (m == 1) { W = Wo;  Wh = WoH;  N = 256; }
    else if (m == 2) { W = Wa;  Wh = WaH;  N = 128; }
    else             { W = Wou; Wh = WouH; N = 256; }
    const int slice = blockIdx.x * 8 + (threadIdx.x >> 5);   // (n8, k16)
    if (slice >= (N / 8) * 16) return;
    const int n8 = slice >> 4, k16 = slice & 15;
    const int lane = threadIdx.x & 31, gid = lane >> 2, tg = lane & 3;
    const int n = n8 * 8 + gid;
    const int k = k16 * 16 + 2 * tg;
    const float w0 = W[(size_t)k * N + n];
    const float w1 = W[(size_t)(k + 1) * N + n];
    const float w2 = W[(size_t)(k + 8) * N + n];
    const float w3 = W[(size_t)(k + 9) * N + n];
    uint2 v;
    v.x = h2u(__floats2half2_rn(w0, w1));
    v.y = h2u(__floats2half2_rn(w2, w3));
    *(uint2*)(Wh + (size_t)slice * 128 + lane * 4) = v;
}

// ------ A matrices: fp32 -> fp16 fragment-native [M/16][k16][lane][8h] -------
__global__ void __launch_bounds__(512)
conv_a(const float* __restrict__ Q, const float* __restrict__ I,
       __half* __restrict__ Qh, __half* __restrict__ Ih) {
    const int blk = blockIdx.x;
    const float* src = blockIdx.y ? I : Q;
    __half* dst      = blockIdx.y ? Ih : Qh;
    const int t = threadIdx.x;
    const int s = t >> 5, lane = t & 31, gid = lane >> 2, tg = lane & 3;
    const size_t r0 = (size_t)(blk * 16 + gid) * 256;
    const size_t r1 = r0 + 8 * 256;
    const int k = s * 16 + 2 * tg;
    const float2 v0 = *(const float2*)(src + r0 + k);
    const float2 v1 = *(const float2*)(src + r1 + k);
    const float2 v2 = *(const float2*)(src + r0 + k + 8);
    const float2 v3 = *(const float2*)(src + r1 + k + 8);
    uint4 o;
    o.x = h2u(__floats2half2_rn(v0.x, v0.y));
    o.y = h2u(__floats2half2_rn(v1.x, v1.y));
    o.z = h2u(__floats2half2_rn(v2.x, v2.y));
    o.w = h2u(__floats2half2_rn(v3.x, v3.y));
    *(uint4*)(dst + ((size_t)(blk * 16 + s) * 32 + lane) * 8) = o;
}

// ---------------- fp16 tensor-core GEMM --------------------------------------
// CTA 128x128, BK=32 (2 k16), 8 warps (2m x 4n), warp 64x32 (16x m16n8k16).
// Fragment-native operands; double-buffered cp.async bulk copies.
#define STAGE_B 16384                 // 8KB A + 8KB B
#define SMEM_HB (2 * STAGE_B)

__global__ void __launch_bounds__(256, 2)
gemm_fp16(const __half* __restrict__ A0, const __half* __restrict__ A1,
          const __half* __restrict__ W0, const __half* __restrict__ W1,
          const __half* __restrict__ W2,
          const float* __restrict__ b0, const float* __restrict__ b1,
          const float* __restrict__ b2,
          float* __restrict__ C0, float* __restrict__ C1, float* __restrict__ C2,
          int fused) {
    extern __shared__ char smc[];
    const int tid  = threadIdx.x;
    const int wid  = tid >> 5;
    const int lane = tid & 31;
    const int gid  = lane >> 2;
    const int tg   = lane & 3;
    const int bm   = blockIdx.x * 128;

    const __half *A, *Wt; const float* bias; float* C; int NTOT = 256; int bn;
    {
        const int y = blockIdx.y;
        if (fused) {
            if (y < 2)      { A = A0; Wt = W0; bias = b0; C = C0; bn = y * 128; }
            else if (y < 4) { A = A1; Wt = W1; bias = b1; C = C1; bn = (y - 2) * 128; }
            else            { A = A1; Wt = W2; bias = b2; C = C2; bn = 0; NTOT = 128; }
        } else              { A = A0; Wt = W0; bias = b0; C = C0; bn = y * 128; }
    }
    const int m_blk_base = bm >> 4;
    const int n_blk_base = bn >> 3;
    const uint32_t smb = smem_u32(smc);

    auto load_tile = [&](int buf, int c) {
        const uint32_t sA = smb + buf * STAGE_B;
        const uint32_t sB = sA + 8192;
#pragma unroll
        for (int i = 0; i < 2; ++i) {
            const int u = tid + i * 256;          // 0..511
            {   // A: 16 slices x 512B
                const int ml = u >> 6, sl = (u >> 5) & 1, wi = u & 31;
                cp_async16(sA + (uint32_t)(((ml * 2 + sl) * 32 + wi) * 16),
                    A + ((size_t)(m_blk_base + ml) * 16 + (2 * c + sl)) * 256 + wi * 8);
            }
            {   // B: 32 slices x 256B
                const int nl = u >> 5, sl = (u >> 4) & 1, wi = u & 15;
                cp_async16(sB + (uint32_t)(((nl * 2 + sl) * 16 + wi) * 16),
                    Wt + ((size_t)(n_blk_base + nl) * 16 + (2 * c + sl)) * 128 + wi * 8);
            }
        }
        CP_COMMIT();
    };

    float acc[4][4][4];
#pragma unroll
    for (int mt = 0; mt < 4; ++mt)
#pragma unroll
        for (int nt = 0; nt < 4; ++nt)
#pragma unroll
            for (int i = 0; i < 4; ++i) acc[mt][nt][i] = 0.0f;

    load_tile(0, 0);
#pragma unroll 1
    for (int c = 0; c < 8; ++c) {
        if (c < 7) { load_tile((c + 1) & 1, c + 1); CP_WAIT(1); }
        else       { CP_WAIT(0); }
        __syncthreads();

        const char* As = smc + (c & 1) * STAGE_B;
        const char* Bs = As + 8192;
#pragma unroll
        for (int s = 0; s < 2; ++s) {
            uint2 bf[4];
#pragma unroll
            for (int nt = 0; nt < 4; ++nt) {
                const int nl = (wid & 3) * 4 + nt;
                bf[nt] = *(const uint2*)(Bs + (((nl * 2 + s) * 32 + lane) * 8));
            }
            uint4 af[4];
#pragma unroll
            for (int mt = 0; mt < 4; ++mt) {
                const int ml = (wid >> 2) * 4 + mt;
                af[mt] = *(const uint4*)(As + (((ml * 2 + s) * 32 + lane) * 16));
            }
#pragma unroll
            for (int mt = 0; mt < 4; ++mt)
#pragma unroll
                for (int nt = 0; nt < 4; ++nt)
                    mma_f16(acc[mt][nt], (const uint32_t*)&af[mt], (const uint32_t*)&bf[nt]);
        }
        __syncthreads();
    }

    const int mbase = (wid >> 2) * 64;
    const int nbase = (wid & 3) * 32;
#pragma unroll
    for (int mt = 0; mt < 4; ++mt) {
        const int row0 = bm + mbase + mt * 16 + gid;
#pragma unroll
        for (int nt = 0; nt < 4; ++nt) {
            const int col = bn + nbase + nt * 8 + tg * 2;
            const float2 bv = *(const float2*)(bias + col);
            float2 v0, v1;
            v0.x = acc[mt][nt][0] + bv.x;  v0.y = acc[mt][nt][1] + bv.y;
            v1.x = acc[mt][nt][2] + bv.x;  v1.y = acc[mt][nt][3] + bv.y;
            *(float2*)(C + (size_t)row0 * NTOT + col)       = v0;
            *(float2*)(C + (size_t)(row0 + 8) * NTOT + col) = v1;
        }
    }
}

// ---------------- sampling ---------------------------------------------------
__global__ void __launch_bounds__(256)
msda_sample(const float* __restrict__ refp) {
    const int bq   = blockIdx.x;
    const int b    = bq / LEN_Q;
    const int tid  = threadIdx.x;
    const int h    = tid >> 5;
    const int lane = tid & 31;

    __shared__ uint4 s_pk[8][16][2];

    const size_t rowo = (size_t)bq * 256;

    {
        const int ln = lane & 15;           // point id
        const int l  = ln >> 2;             // level

        float logit = g_attn[(size_t)bq * 128 + h * 16 + ln];
        float m = logit;
#pragma unroll
        for (int s = 8; s; s >>= 1) m = fmaxf(m, __shfl_xor_sync(0xffffffffu, m, s, 16));
        float e = __expf(logit - m);
        float ssum = e;
#pragma unroll
        for (int s = 8; s; s >>= 1) ssum += __shfl_xor_sync(0xffffffffu, ssum, s, 16);
        const float aw = e / ssum;

        const int S  = 64 >> l;
        const int st = (l == 0) ? 0 : (l == 1) ? 4096 : (l == 2) ? 5120 : 5376;
        const float fs = (float)S;

        const float rx = refp[(size_t)bq * 8 + l * 2 + 0];
        const float ry = refp[(size_t)bq * 8 + l * 2 + 1];
        const float ox = g_off[rowo + h * 32 + ln * 2 + 0];
        const float oy = g_off[rowo + h * 32 + ln * 2 + 1];

        const float x = fmaf(rx, fs, ox) - 0.5f;
        const float y = fmaf(ry, fs, oy) - 0.5f;
        const float x0f = floorf(x), y0f = floorf(y);
        const int ix0 = (int)x0f, iy0 = (int)y0f;
        const float wx = x - x0f, wy = y - y0f;

        const float fx0 = (unsigned)ix0       < (unsigned)S ? 1.0f : 0.0f;
        const float fx1 = (unsigned)(ix0 + 1) < (unsigned)S ? 1.0f : 0.0f;
        const float fy0 = (unsigned)iy0       < (unsigned)S ? 1.0f : 0.0f;
        const float fy1 = (unsigned)(iy0 + 1) < (unsigned)S ? 1.0f : 0.0f;

        const int cx0 = min(max(ix0, 0), S - 1);
        const int cx1 = min(max(ix0 + 1, 0), S - 1);
        const int cy0 = min(max(iy0, 0), S - 1);
        const int cy1 = min(max(iy0 + 1, 0), S - 1);

        if (lane < 16) {
            uint4 left, right;
            left.x  = (uint32_t)((st + cy0 * S + cx0) * 256);
            left.y  = (uint32_t)((st + cy1 * S + cx0) * 256);
            left.z  = __float_as_uint(aw * (1.0f - wx) * (1.0f - wy) * fx0 * fy0);
            left.w  = __float_as_uint(aw * (1.0f - wx) * wy          * fx0 * fy1);
            right.x = (uint32_t)((st + cy0 * S + cx1) * 256);
            right.y = (uint32_t)((st + cy1 * S + cx1) * 256);
            right.z = __float_as_uint(aw * wx * (1.0f - wy) * fx1 * fy0);
            right.w = __float_as_uint(aw * wx * wy          * fx1 * fy1);
            s_pk[h][ln][0] = left;
            s_pk[h][ln][1] = right;
        }
    }
    __syncwarp();

    const int side = lane >> 4;
    const int cb   = (lane & 15) * 2;       // channel pair within head
    const float* vb = g_value + (size_t)b * (LEN_IN * 256) + h * 32 + cb;

    float a0 = 0.f, a1 = 0.f, a2 = 0.f, a3 = 0.f;
#pragma unroll
    for (int p = 0; p < 16; ++p) {
        const uint4 pk = s_pk[h][p][side];
        const float2 vt = *(const float2*)(vb + pk.x);
        const float2 vo = *(const float2*)(vb + pk.y);
        const float wt = __uint_as_float(pk.z);
        const float wb = __uint_as_float(pk.w);
        a0 = fmaf(wt, vt.x, a0);
        a1 = fmaf(wt, vt.y, a1);
        a2 = fmaf(wb, vo.x, a2);
        a3 = fmaf(wb, vo.y, a3);
    }
    float ox_ = a0 + a2;
    float oy_ = a1 + a3;
    ox_ += __shfl_xor_sync(0xffffffffu, ox_, 16);
    oy_ += __shfl_xor_sync(0xffffffffu, oy_, 16);

    if (lane < 16) {   // store fp16 at fragment-native position
        const int c  = h * 16 + (lane & 15);   // global k-pair index 0..127
        const int g  = bq & 15;
        const int fl = (g & 7) * 4 + (c & 3);            // lane within frag
        const int slot = (g >> 3) + ((c >> 2) & 1) * 2;  // half2 slot 0..3
        const size_t h2i = ((size_t)((bq >> 4) * 16 + (c >> 3)) * 32 + fl) * 4 + slot;
        ((__half2*)g_midh)[h2i] = __floats2half2_rn(ox_, oy_);
    }
}

// ---------------- launch -----------------------------------------------------
extern "C" void kernel_launch(void* const* d_in, const int* in_sizes, int n_in,
                              void* d_out, int out_size) {
    const float* query   = (const float*)d_in[0];
    const float* refp    = (const float*)d_in[1];
    const float* in_flat = (const float*)d_in[2];
    const float* W_val  = (const float*)d_in[5];
    const float* b_val  = (const float*)d_in[6];
    const float* W_off  = (const float*)d_in[7];
    const float* b_off  = (const float*)d_in[8];
    const float* W_attn = (const float*)d_in[9];
    const float* b_attn = (const float*)d_in[10];
    const float* W_out  = (const float*)d_in[11];
    const float* b_out  = (const float*)d_in[12];
    float* out = (float*)d_out;

    float *pv, *po, *pa;
    __half *qh, *ih, *mh, *wvH, *woH, *waH, *wouH;
    cudaGetSymbolAddress((void**)&pv,  g_value);
    cudaGetSymbolAddress((void**)&po,  g_off);
    cudaGetSymbolAddress((void**)&pa,  g_attn);
    cudaGetSymbolAddress((void**)&qh,  g_qh);
    cudaGetSymbolAddress((void**)&ih,  g_ih);
    cudaGetSymbolAddress((void**)&mh,  g_midh);
    cudaGetSymbolAddress((void**)&wvH, g_wvH);
    cudaGetSymbolAddress((void**)&woH, g_woH);
    cudaGetSymbolAddress((void**)&waH, g_waH);
    cudaGetSymbolAddress((void**)&wouH, g_wouH);

    cudaFuncSetAttribute(gemm_fp16, cudaFuncAttributeMaxDynamicSharedMemorySize, SMEM_HB);

    conv_w<<<dim3(64, 4), 256>>>(W_val, W_off, W_attn, W_out, wvH, woH, waH, wouH);
    conv_a<<<dim3(M_TOTAL / 16, 2), 512>>>(query, in_flat, qh, ih);

    // fused front GEMMs: value (y=0,1), offsets (y=2,3), attn (y=4)
    gemm_fp16<<<dim3(M_TOTAL / 128, 5), 256, SMEM_HB>>>(
        ih, qh, wvH, woH, waH, b_val, b_off, b_attn, pv, po, pa, 1);

    msda_sample<<<M_TOTAL, 256>>>(refp);

    // output projection
    gemm_fp16<<<dim3(M_TOTAL / 128, 2), 256, SMEM_HB>>>(
        mh, nullptr, wouH, nullptr, nullptr, b_out, nullptr, nullptr,
        out, nullptr, nullptr, 0);
}

// round 15
// speedup vs baseline: 1.3439x; 1.0367x over previous
#include <cuda_runtime.h>
#include <cuda_fp16.h>
#include <cstdint>
#include <math.h>

#define D_MODEL   256
#define N_HEADS   8
#define LEN_IN    5440
#define LEN_Q     5440
#define BATCH     4
#define M_TOTAL   (BATCH * LEN_Q)   // 21760 = 1360 * 16

// ---------------- scratch (static device globals; no allocation) -------------
__device__ float g_off  [(size_t)M_TOTAL * 256];
__device__ float g_attn [(size_t)M_TOTAL * 128];
// fp16 value (row-major, written by value GEMM, read by sampling)
__device__ __align__(16) __half g_valueH[(size_t)M_TOTAL * 256];
// fp16 fragment-native A operands: [M/16][16 k16][32 lanes][8 halfs]
__device__ __align__(16) __half g_qh [(size_t)M_TOTAL * 256];
__device__ __align__(16) __half g_ih [(size_t)M_TOTAL * 256];
__device__ __align__(16) __half g_midh[(size_t)M_TOTAL * 256];
// fp16 fragment-native weights: [N/8][16 k16][32 lanes][4 halfs]
__device__ __align__(16) __half g_wvH [256 * 256];
__device__ __align__(16) __half g_woH [256 * 256];
__device__ __align__(16) __half g_waH [128 * 256];
__device__ __align__(16) __half g_wouH[256 * 256];

// ---------------- PTX helpers ------------------------------------------------
__device__ __forceinline__ uint32_t h2u(__half2 h) {
    return *reinterpret_cast<uint32_t*>(&h);
}
__device__ __forceinline__ uint32_t smem_u32(const void* p) {
    uint32_t a;
    asm("{ .reg .u64 t; cvta.to.shared.u64 t, %1; cvt.u32.u64 %0, t; }" : "=r"(a) : "l"(p));
    return a;
}
__device__ __forceinline__ void cp_async16(uint32_t dst, const void* src) {
    asm volatile("cp.async.cg.shared.global [%0], [%1], 16;" :: "r"(dst), "l"(src));
}
#define CP_COMMIT() asm volatile("cp.async.commit_group;" ::: "memory")
#define CP_WAIT(n)  asm volatile("cp.async.wait_group %0;" :: "n"(n) : "memory")

__device__ __forceinline__ void mma_f16(float* c, const uint32_t* a, const uint32_t* b) {
    asm volatile("mma.sync.aligned.m16n8k16.row.col.f32.f16.f16.f32 "
        "{%0,%1,%2,%3}, {%4,%5,%6,%7}, {%8,%9}, {%0,%1,%2,%3};"
        : "+f"(c[0]), "+f"(c[1]), "+f"(c[2]), "+f"(c[3])
        : "r"(a[0]), "r"(a[1]), "r"(a[2]), "r"(a[3]), "r"(b[0]), "r"(b[1]));
}

// ------ weights: transpose + fp16 + fragment-native [N/8][k16][lane][4h] -----
__global__ void conv_w(const float* __restrict__ Wv, const float* __restrict__ Wo,
                       const float* __restrict__ Wa, const float* __restrict__ Wou,
                       __half* __restrict__ WvH, __half* __restrict__ WoH,
                       __half* __restrict__ WaH, __half* __restrict__ WouH) {
    const int m = blockIdx.y;
    const float* W; __half* Wh; int N;
    if      (m == 0) { W = Wv;  Wh = WvH;  N = 256; }
    else if (m == 1) { W = Wo;  Wh = WoH;  N = 256; }
    else if (m == 2) { W = Wa;  Wh = WaH;  N = 128; }
    else             { W = Wou; Wh = WouH; N = 256; }
    const int slice = blockIdx.x * 8 + (threadIdx.x >> 5);   // (n8, k16)
    if (slice >= (N / 8) * 16) return;
    const int n8 = slice >> 4, k16 = slice & 15;
    const int lane = threadIdx.x & 31, gid = lane >> 2, tg = lane & 3;
    const int n = n8 * 8 + gid;
    const int k = k16 * 16 + 2 * tg;
    const float w0 = W[(size_t)k * N + n];
    const float w1 = W[(size_t)(k + 1) * N + n];
    const float w2 = W[(size_t)(k + 8) * N + n];
    const float w3 = W[(size_t)(k + 9) * N + n];
    uint2 v;
    v.x = h2u(__floats2half2_rn(w0, w1));
    v.y = h2u(__floats2half2_rn(w2, w3));
    *(uint2*)(Wh + (size_t)slice * 128 + lane * 4) = v;
}

// ------ A matrices: fp32 -> fp16 fragment-native [M/16][k16][lane][8h] -------
__global__ void __launch_bounds__(512)
conv_a(const float* __restrict__ Q, const float* __restrict__ I,
       __half* __restrict__ Qh, __half* __restrict__ Ih) {
    const int blk = blockIdx.x;
    const float* src = blockIdx.y ? I : Q;
    __half* dst      = blockIdx.y ? Ih : Qh;
    const int t = threadIdx.x;
    const int s = t >> 5, lane = t & 31, gid = lane >> 2, tg = lane & 3;
    const size_t r0 = (size_t)(blk * 16 + gid) * 256;
    const size_t r1 = r0 + 8 * 256;
    const int k = s * 16 + 2 * tg;
    const float2 v0 = *(const float2*)(src + r0 + k);
    const float2 v1 = *(const float2*)(src + r1 + k);
    const float2 v2 = *(const float2*)(src + r0 + k + 8);
    const float2 v3 = *(const float2*)(src + r1 + k + 8);
    uint4 o;
    o.x = h2u(__floats2half2_rn(v0.x, v0.y));
    o.y = h2u(__floats2half2_rn(v1.x, v1.y));
    o.z = h2u(__floats2half2_rn(v2.x, v2.y));
    o.w = h2u(__floats2half2_rn(v3.x, v3.y));
    *(uint4*)(dst + ((size_t)(blk * 16 + s) * 32 + lane) * 8) = o;
}

// ---------------- fp16 tensor-core GEMM --------------------------------------
// CTA 128x128, BK=32 (2 k16), 8 warps (2m x 4n), warp 64x32 (16x m16n8k16).
// fused: y0,1 value -> fp16 C; y2,3 offsets -> fp32; y4 attn -> fp32.
#define STAGE_B 16384                 // 8KB A + 8KB B
#define SMEM_HB (2 * STAGE_B)

__global__ void __launch_bounds__(256, 2)
gemm_fp16(const __half* __restrict__ A0, const __half* __restrict__ A1,
          const __half* __restrict__ W0, const __half* __restrict__ W1,
          const __half* __restrict__ W2,
          const float* __restrict__ b0, const float* __restrict__ b1,
          const float* __restrict__ b2,
          __half* __restrict__ CH, float* __restrict__ C1, float* __restrict__ C2,
          float* __restrict__ CF, int fused) {
    extern __shared__ char smc[];
    const int tid  = threadIdx.x;
    const int wid  = tid >> 5;
    const int lane = tid & 31;
    const int gid  = lane >> 2;
    const int tg   = lane & 3;
    const int bm   = blockIdx.x * 128;

    const __half *A, *Wt; const float* bias; int NTOT = 256; int bn;
    float* Cf = nullptr; __half* Ch = nullptr;
    {
        const int y = blockIdx.y;
        if (fused) {
            if (y < 2)      { A = A0; Wt = W0; bias = b0; Ch = CH; bn = y * 128; }
            else if (y < 4) { A = A1; Wt = W1; bias = b1; Cf = C1; bn = (y - 2) * 128; }
            else            { A = A1; Wt = W2; bias = b2; Cf = C2; bn = 0; NTOT = 128; }
        } else              { A = A0; Wt = W0; bias = b0; Cf = CF; bn = y * 128; }
    }
    const int m_blk_base = bm >> 4;
    const int n_blk_base = bn >> 3;
    const uint32_t smb = smem_u32(smc);

    auto load_tile = [&](int buf, int c) {
        const uint32_t sA = smb + buf * STAGE_B;
        const uint32_t sB = sA + 8192;
#pragma unroll
        for (int i = 0; i < 2; ++i) {
            const int u = tid + i * 256;          // 0..511
            {   // A: 16 slices x 512B
                const int ml = u >> 6, sl = (u >> 5) & 1, wi = u & 31;
                cp_async16(sA + (uint32_t)(((ml * 2 + sl) * 32 + wi) * 16),
                    A + ((size_t)(m_blk_base + ml) * 16 + (2 * c + sl)) * 256 + wi * 8);
            }
            {   // B: 32 slices x 256B
                const int nl = u >> 5, sl = (u >> 4) & 1, wi = u & 15;
                cp_async16(sB + (uint32_t)(((nl * 2 + sl) * 16 + wi) * 16),
                    Wt + ((size_t)(n_blk_base + nl) * 16 + (2 * c + sl)) * 128 + wi * 8);
            }
        }
        CP_COMMIT();
    };

    float acc[4][4][4];
#pragma unroll
    for (int mt = 0; mt < 4; ++mt)
#pragma unroll
        for (int nt = 0; nt < 4; ++nt)
#pragma unroll
            for (int i = 0; i < 4; ++i) acc[mt][nt][i] = 0.0f;

    load_tile(0, 0);
#pragma unroll 1
    for (int c = 0; c < 8; ++c) {
        if (c < 7) { load_tile((c + 1) & 1, c + 1); CP_WAIT(1); }
        else       { CP_WAIT(0); }
        __syncthreads();

        const char* As = smc + (c & 1) * STAGE_B;
        const char* Bs = As + 8192;
#pragma unroll
        for (int s = 0; s < 2; ++s) {
            uint2 bf[4];
#pragma unroll
            for (int nt = 0; nt < 4; ++nt) {
                const int nl = (wid & 3) * 4 + nt;
                bf[nt] = *(const uint2*)(Bs + (((nl * 2 + s) * 32 + lane) * 8));
            }
            uint4 af[4];
#pragma unroll
            for (int mt = 0; mt < 4; ++mt) {
                const int ml = (wid >> 2) * 4 + mt;
                af[mt] = *(const uint4*)(As + (((ml * 2 + s) * 32 + lane) * 16));
            }
#pragma unroll
            for (int mt = 0; mt < 4; ++mt)
#pragma unroll
                for (int nt = 0; nt < 4; ++nt)
                    mma_f16(acc[mt][nt], (const uint32_t*)&af[mt], (const uint32_t*)&bf[nt]);
        }
        __syncthreads();
    }

    const int mbase = (wid >> 2) * 64;
    const int nbase = (wid & 3) * 32;
#pragma unroll
    for (int mt = 0; mt < 4; ++mt) {
        const int row0 = bm + mbase + mt * 16 + gid;
#pragma unroll
        for (int nt = 0; nt < 4; ++nt) {
            const int col = bn + nbase + nt * 8 + tg * 2;
            const float2 bv = *(const float2*)(bias + col);
            const float c0 = acc[mt][nt][0] + bv.x, c1 = acc[mt][nt][1] + bv.y;
            const float c2 = acc[mt][nt][2] + bv.x, c3 = acc[mt][nt][3] + bv.y;
            if (Ch) {
                *(uint32_t*)(Ch + (size_t)row0 * 256 + col)       = h2u(__floats2half2_rn(c0, c1));
                *(uint32_t*)(Ch + (size_t)(row0 + 8) * 256 + col) = h2u(__floats2half2_rn(c2, c3));
            } else {
                *(float2*)(Cf + (size_t)row0 * NTOT + col)       = make_float2(c0, c1);
                *(float2*)(Cf + (size_t)(row0 + 8) * NTOT + col) = make_float2(c2, c3);
            }
        }
    }
}

// ---------------- sampling (fp16 value gathers, fp32 math) -------------------
__global__ void __launch_bounds__(256)
msda_sample(const float* __restrict__ refp) {
    const int bq   = blockIdx.x;
    const int b    = bq / LEN_Q;
    const int tid  = threadIdx.x;
    const int h    = tid >> 5;
    const int lane = tid & 31;

    __shared__ uint4 s_pk[8][16][2];

    const size_t rowo = (size_t)bq * 256;

    {
        const int ln = lane & 15;           // point id
        const int l  = ln >> 2;             // level

        float logit = g_attn[(size_t)bq * 128 + h * 16 + ln];
        float m = logit;
#pragma unroll
        for (int s = 8; s; s >>= 1) m = fmaxf(m, __shfl_xor_sync(0xffffffffu, m, s, 16));
        float e = __expf(logit - m);
        float ssum = e;
#pragma unroll
        for (int s = 8; s; s >>= 1) ssum += __shfl_xor_sync(0xffffffffu, ssum, s, 16);
        const float aw = e / ssum;

        const int S  = 64 >> l;
        const int st = (l == 0) ? 0 : (l == 1) ? 4096 : (l == 2) ? 5120 : 5376;
        const float fs = (float)S;

        const float rx = refp[(size_t)bq * 8 + l * 2 + 0];
        const float ry = refp[(size_t)bq * 8 + l * 2 + 1];
        const float ox = g_off[rowo + h * 32 + ln * 2 + 0];
        const float oy = g_off[rowo + h * 32 + ln * 2 + 1];

        const float x = fmaf(rx, fs, ox) - 0.5f;
        const float y = fmaf(ry, fs, oy) - 0.5f;
        const float x0f = floorf(x), y0f = floorf(y);
        const int ix0 = (int)x0f, iy0 = (int)y0f;
        const float wx = x - x0f, wy = y - y0f;

        const float fx0 = (unsigned)ix0       < (unsigned)S ? 1.0f : 0.0f;
        const float fx1 = (unsigned)(ix0 + 1) < (unsigned)S ? 1.0f : 0.0f;
        const float fy0 = (unsigned)iy0       < (unsigned)S ? 1.0f : 0.0f;
        const float fy1 = (unsigned)(iy0 + 1) < (unsigned)S ? 1.0f : 0.0f;

        const int cx0 = min(max(ix0, 0), S - 1);
        const int cx1 = min(max(ix0 + 1, 0), S - 1);
        const int cy0 = min(max(iy0, 0), S - 1);
        const int cy1 = min(max(iy0 + 1, 0), S - 1);

        if (lane < 16) {
            uint4 left, right;
            left.x  = (uint32_t)((st + cy0 * S + cx0) * 256);
            left.y  = (uint32_t)((st + cy1 * S + cx0) * 256);
            left.z  = __float_as_uint(aw * (1.0f - wx) * (1.0f - wy) * fx0 * fy0);
            left.w  = __float_as_uint(aw * (1.0f - wx) * wy          * fx0 * fy1);
            right.x = (uint32_t)((st + cy0 * S + cx1) * 256);
            right.y = (uint32_t)((st + cy1 * S + cx1) * 256);
            right.z = __float_as_uint(aw * wx * (1.0f - wy) * fx1 * fy0);
            right.w = __float_as_uint(aw * wx * wy          * fx1 * fy1);
            s_pk[h][ln][0] = left;
            s_pk[h][ln][1] = right;
        }
    }
    __syncwarp();

    const int side = lane >> 4;
    const int cb   = (lane & 15) * 2;       // channel pair within head
    const __half* vb = g_valueH + (size_t)b * (LEN_IN * 256) + h * 32 + cb;

    float a0 = 0.f, a1 = 0.f, a2 = 0.f, a3 = 0.f;
#pragma unroll
    for (int p = 0; p < 16; ++p) {
        const uint4 pk = s_pk[h][p][side];
        const float2 vt = __half22float2(*(const __half2*)(vb + pk.x));
        const float2 vo = __half22float2(*(const __half2*)(vb + pk.y));
        const float wt = __uint_as_float(pk.z);
        const float wb = __uint_as_float(pk.w);
        a0 = fmaf(wt, vt.x, a0);
        a1 = fmaf(wt, vt.y, a1);
        a2 = fmaf(wb, vo.x, a2);
        a3 = fmaf(wb, vo.y, a3);
    }
    float ox_ = a0 + a2;
    float oy_ = a1 + a3;
    ox_ += __shfl_xor_sync(0xffffffffu, ox_, 16);
    oy_ += __shfl_xor_sync(0xffffffffu, oy_, 16);

    if (lane < 16) {   // store fp16 at fragment-native position
        const int c  = h * 16 + (lane & 15);   // global k-pair index 0..127
        const int g  = bq & 15;
        const int fl = (g & 7) * 4 + (c & 3);            // lane within frag
        const int slot = (g >> 3) + ((c >> 2) & 1) * 2;  // half2 slot 0..3
        const size_t h2i = ((size_t)((bq >> 4) * 16 + (c >> 3)) * 32 + fl) * 4 + slot;
        ((__half2*)g_midh)[h2i] = __floats2half2_rn(ox_, oy_);
    }
}

// ---------------- launch -----------------------------------------------------
extern "C" void kernel_launch(void* const* d_in, const int* in_sizes, int n_in,
                              void* d_out, int out_size) {
    const float* query   = (const float*)d_in[0];
    const float* refp    = (const float*)d_in[1];
    const float* in_flat = (const float*)d_in[2];
    const float* W_val  = (const float*)d_in[5];
    const float* b_val  = (const float*)d_in[6];
    const float* W_off  = (const float*)d_in[7];
    const float* b_off  = (const float*)d_in[8];
    const float* W_attn = (const float*)d_in[9];
    const float* b_attn = (const float*)d_in[10];
    const float* W_out  = (const float*)d_in[11];
    const float* b_out  = (const float*)d_in[12];
    float* out = (float*)d_out;

    float *po, *pa;
    __half *vh, *qh, *ih, *mh, *wvH, *woH, *waH, *wouH;
    cudaGetSymbolAddress((void**)&po,  g_off);
    cudaGetSymbolAddress((void**)&pa,  g_attn);
    cudaGetSymbolAddress((void**)&vh,  g_valueH);
    cudaGetSymbolAddress((void**)&qh,  g_qh);
    cudaGetSymbolAddress((void**)&ih,  g_ih);
    cudaGetSymbolAddress((void**)&mh,  g_midh);
    cudaGetSymbolAddress((void**)&wvH, g_wvH);
    cudaGetSymbolAddress((void**)&woH, g_woH);
    cudaGetSymbolAddress((void**)&waH, g_waH);
    cudaGetSymbolAddress((void**)&wouH, g_wouH);

    cudaFuncSetAttribute(gemm_fp16, cudaFuncAttributeMaxDynamicSharedMemorySize, SMEM_HB);

    conv_w<<<dim3(64, 4), 256>>>(W_val, W_off, W_attn, W_out, wvH, woH, waH, wouH);
    conv_a<<<dim3(M_TOTAL / 16, 2), 512>>>(query, in_flat, qh, ih);

    // fused front GEMMs: value (y=0,1 -> fp16), offsets (y=2,3), attn (y=4)
    gemm_fp16<<<dim3(M_TOTAL / 128, 5), 256, SMEM_HB>>>(
        ih, qh, wvH, woH, waH, b_val, b_off, b_attn, vh, po, pa, nullptr, 1);

    msda_sample<<<M_TOTAL, 256>>>(refp);

    // output projection (fp32 out)
    gemm_fp16<<<dim3(M_TOTAL / 128, 2), 256, SMEM_HB>>>(
        mh, nullptr, wouH, nullptr, nullptr, b_out, nullptr, nullptr,
        nullptr, nullptr, nullptr, out, 0);
}